// round 6
// baseline (speedup 1.0000x reference)
#include <cuda_runtime.h>
#include <cuda_bf16.h>
#include <cstdint>

#define BATCH    1024
#define TOT      4096
#define SEN      1024
#define CNNOUT   3264
#define NOUT     1968
#define NOUT_PAD 2048

// ---------------- scratch device globals (no allocations) -------------------
__device__ __align__(256) __nv_bfloat16 g_featH[(size_t)BATCH * CNNOUT];
__device__ __align__(256) __nv_bfloat16 g_featL[(size_t)BATCH * CNNOUT];
__device__ __align__(256) __nv_bfloat16 g_ipwH [(size_t)SEN * CNNOUT];
__device__ __align__(256) __nv_bfloat16 g_ipwL [(size_t)SEN * CNNOUT];
__device__ __align__(256) __nv_bfloat16 g_WH   [(size_t)TOT * TOT];
__device__ __align__(256) __nv_bfloat16 g_WL   [(size_t)TOT * TOT];
__device__ __align__(256) __nv_bfloat16 g_owH  [(size_t)NOUT_PAD * 1024];
__device__ __align__(256) __nv_bfloat16 g_owL  [(size_t)NOUT_PAD * 1024];
__device__ __align__(256) __nv_bfloat16 g_P0H  [(size_t)BATCH * TOT];
__device__ __align__(256) __nv_bfloat16 g_P0L  [(size_t)BATCH * TOT];
__device__ __align__(256) __nv_bfloat16 g_P1H  [(size_t)BATCH * TOT];
__device__ __align__(256) __nv_bfloat16 g_P1L  [(size_t)BATCH * TOT];
__device__ __align__(256) __nv_bfloat16 g_OPH  [(size_t)BATCH * 1024];
__device__ __align__(256) __nv_bfloat16 g_OPL  [(size_t)BATCH * 1024];
__device__ __align__(256) __nv_bfloat16 g_laH [(size_t)TOT * 64];
__device__ __align__(256) __nv_bfloat16 g_laL [(size_t)TOT * 64];
__device__ __align__(256) __nv_bfloat16 g_lbtH[(size_t)TOT * 64];
__device__ __align__(256) __nv_bfloat16 g_lbtL[(size_t)TOT * 64];

// ---------------- helpers ----------------------------------------------------
__device__ __forceinline__ uint32_t smem_u32(const void* p) {
    uint32_t a;
    asm("{ .reg .u64 t; cvta.to.shared.u64 t, %1; cvt.u32.u64 %0, t; }" : "=r"(a) : "l"(p));
    return a;
}
__device__ __forceinline__ void cpa(uint32_t dst, const void* src) {
    asm volatile("cp.async.cg.shared.global [%0], [%1], 16;" :: "r"(dst), "l"(src));
}
#define CP_COMMIT() asm volatile("cp.async.commit_group;")
#define CP_WAIT0()  asm volatile("cp.async.wait_group 0;")
#define CP_WAIT1()  asm volatile("cp.async.wait_group 1;")
#define CP_WAIT2()  asm volatile("cp.async.wait_group 2;")

__device__ __forceinline__ void ldsm4(uint32_t* r, uint32_t addr) {
    asm volatile("ldmatrix.sync.aligned.m8n8.x4.shared.b16 {%0,%1,%2,%3}, [%4];"
                 : "=r"(r[0]), "=r"(r[1]), "=r"(r[2]), "=r"(r[3]) : "r"(addr));
}
__device__ __forceinline__ void mma16816(float* c, const uint32_t* a, const uint32_t* b) {
    asm volatile("mma.sync.aligned.m16n8k16.row.col.f32.bf16.bf16.f32 "
                 "{%0,%1,%2,%3}, {%4,%5,%6,%7}, {%8,%9}, {%0,%1,%2,%3};"
                 : "+f"(c[0]), "+f"(c[1]), "+f"(c[2]), "+f"(c[3])
                 : "r"(a[0]), "r"(a[1]), "r"(a[2]), "r"(a[3]), "r"(b[0]), "r"(b[1]));
}

__device__ __forceinline__ void split8(const float* v, uint4& uh, uint4& ul) {
    uint32_t h[4], l[4];
#pragma unroll
    for (int q = 0; q < 4; q++) {
        __nv_bfloat16 b0 = __float2bfloat16(v[2 * q]);
        __nv_bfloat16 b1 = __float2bfloat16(v[2 * q + 1]);
        float r0 = v[2 * q]     - __bfloat162float(b0);
        float r1 = v[2 * q + 1] - __bfloat162float(b1);
        __nv_bfloat16 c0 = __float2bfloat16(r0);
        __nv_bfloat16 c1 = __float2bfloat16(r1);
        h[q] = (uint32_t)__bfloat16_as_ushort(b0) | ((uint32_t)__bfloat16_as_ushort(b1) << 16);
        l[q] = (uint32_t)__bfloat16_as_ushort(c0) | ((uint32_t)__bfloat16_as_ushort(c1) << 16);
    }
    uh = make_uint4(h[0], h[1], h[2], h[3]);
    ul = make_uint4(l[0], l[1], l[2], l[3]);
}
__device__ __forceinline__ void pack2(float v0, float v1, uint32_t& ph, uint32_t& pl) {
    __nv_bfloat16 h0 = __float2bfloat16(v0);
    __nv_bfloat16 h1 = __float2bfloat16(v1);
    __nv_bfloat16 q0 = __float2bfloat16(v0 - __bfloat162float(h0));
    __nv_bfloat16 q1 = __float2bfloat16(v1 - __bfloat162float(h1));
    ph = (uint32_t)__bfloat16_as_ushort(h0) | ((uint32_t)__bfloat16_as_ushort(h1) << 16);
    pl = (uint32_t)__bfloat16_as_ushort(q0) | ((uint32_t)__bfloat16_as_ushort(q1) << 16);
}
__device__ __forceinline__ float bflo(uint32_t u) {
    return __bfloat162float(__ushort_as_bfloat16((unsigned short)(u & 0xFFFF)));
}
__device__ __forceinline__ float bfhi(uint32_t u) {
    return __bfloat162float(__ushort_as_bfloat16((unsigned short)(u >> 16)));
}

// ---------------- conv feature extraction -> hi/lo row-major ----------------
struct ConvPtrs { const float* w[8]; };

__global__ void conv_feat_kernel(const float* __restrict__ x, ConvPtrs cw,
                                 const float* __restrict__ conv_b,
                                 __nv_bfloat16* __restrict__ fH,
                                 __nv_bfloat16* __restrict__ fL)
{
    __shared__ float xs[512];
    const int b = blockIdx.x;
    const float* xb = x + b * 512;
    for (int i = threadIdx.x; i < 512; i += 256) xs[i] = xb[i];
    __syncthreads();

    const int offs[9] = {0, 1024, 1808, 2384, 2784, 3040, 3184, 3248, 3264};

    for (int o = threadIdx.x; o < CNNOUT; o += 256) {
        int k = 1;
        while (o >= offs[k]) k++;
        int local = o - offs[k - 1];
        int H = 9 - k;
        int f = local / (H * H);
        int rem = local - f * H * H;
        int i0 = rem / H;
        int j0 = rem - i0 * H;

        const float* w = cw.w[k - 1] + f * 8 * k * k;
        float acc = conv_b[(k - 1) * 16 + f];
        for (int c = 0; c < 8; c++) {
            const float* wc = w + c * k * k;
            for (int p = 0; p < k; p++)
                for (int q = 0; q < k; q++)
                    acc += xs[((i0 + p) * 8 + (j0 + q)) * 8 + c] * wc[p * k + q];
        }
        float e = fmaxf(acc, 0.0f);
        __nv_bfloat16 bh = __float2bfloat16(e);
        __nv_bfloat16 bl = __float2bfloat16(e - __bfloat162float(bh));
        fH[(size_t)b * CNNOUT + o] = bh;
        fL[(size_t)b * CNNOUT + o] = bl;
    }
}

// ---------------- pack [K,N] fp32 weight transposed -> [N,K] hi/lo bf16 -----
__global__ __launch_bounds__(256) void pack_wT(const float* __restrict__ w,
                                               int ldw, int ntrue, int ldk,
                                               __nv_bfloat16* __restrict__ H,
                                               __nv_bfloat16* __restrict__ L)
{
    __shared__ float sm[64 * 65];
    const int k0 = blockIdx.x * 64, n0 = blockIdx.y * 64;
    const int tid = threadIdx.x;

    for (int i = tid; i < 4096; i += 256) {
        int k = i >> 6, n = i & 63;
        int gn = n0 + n;
        sm[k * 65 + n] = (gn < ntrue) ? w[(size_t)(k0 + k) * ldw + gn] : 0.0f;
    }
    __syncthreads();

    for (int it = tid; it < 512; it += 256) {
        int n = it & 63, kg = it >> 6;
        float v[8];
#pragma unroll
        for (int j = 0; j < 8; j++) v[j] = sm[(kg * 8 + j) * 65 + n];
        uint4 uh, ul;
        split8(v, uh, ul);
        size_t o = (size_t)(n0 + n) * ldk + k0 + kg * 8;
        *(uint4*)((char*)H + o * 2) = uh;
        *(uint4*)((char*)L + o * 2) = ul;
    }
}

// ---------------- straight split-copy fp32 -> hi/lo bf16 --------------------
__global__ void split_copy(const float* __restrict__ in,
                           __nv_bfloat16* __restrict__ H,
                           __nv_bfloat16* __restrict__ L, int n8)
{
    int i = blockIdx.x * blockDim.x + threadIdx.x;
    if (i >= n8) return;
    float v[8];
    *(float4*)(v)     = *(const float4*)(in + (size_t)i * 8);
    *(float4*)(v + 4) = *(const float4*)(in + (size_t)i * 8 + 4);
    uint4 uh, ul;
    split8(v, uh, ul);
    *(uint4*)((char*)H + (size_t)i * 16) = uh;
    *(uint4*)((char*)L + (size_t)i * 16) = ul;
}

// ---------------- mma.sync bf16-split GEMM ----------------------------------
// Tile: 128 x (NT*32).  3-term split (drop lo*lo).  Warps 2(M) x 4(N).
// KCH: K elements per pipeline chunk (64 or 32). STAGES ring buffers.
// Prologue ALWAYS commits STAGES-1 groups (empty groups act as in-order
// fences; cp.async groups retire FIFO) - required for KB < STAGES-1.
// WEFF mode: acc = lora product; epilogue = mask(W)*(W + 2*acc) -> packed Wt.
template<int NT, int STAGES, int KCH, bool WEFF>
__global__ __launch_bounds__(256, 1)
void mma_gemm(const __nv_bfloat16* __restrict__ AH, const __nv_bfloat16* __restrict__ AL, int lda,
              const __nv_bfloat16* __restrict__ BH, const __nv_bfloat16* __restrict__ BL, int ldb,
              int K,
              const float* __restrict__ bias,
              const __nv_bfloat16* __restrict__ addH, const __nv_bfloat16* __restrict__ addL,
              int add_cols, int ld_add, int do_relu,
              float* __restrict__ outF, int ldF, int ncolF,
              __nv_bfloat16* __restrict__ PH, __nv_bfloat16* __restrict__ PL, int ldP,
              const float* __restrict__ Wsrc)
{
    constexpr int NTILE  = NT * 32;
    constexpr int GPC    = KCH / 8;            // 16B granules per row per chunk
    constexpr int ABYTES = 128 * KCH * 2;      // one A half (hi or lo)
    constexpr int BBYTES = NTILE * KCH * 2;    // one B half
    constexpr int STG_BYTES = 2 * ABYTES + 2 * BBYTES;
    extern __shared__ __align__(128) char smc[];

    const int tid = threadIdx.x, l = tid & 31, wid = tid >> 5;
    const int nblk = blockIdx.x, mblk = blockIdx.y;
    const int KB = K / KCH;
    const uint32_t smb = smem_u32(smc);
    const int mrow0 = mblk * 128;
    const int nrow0 = nblk * NTILE;

    // swizzled byte offset of granule g in row r (row stride = KCH*2 bytes)
    auto swof = [](int r, uint32_t g) -> uint32_t {
        if (KCH == 64) return (uint32_t)r * 128 + ((g ^ (uint32_t)(r & 7)) << 4);
        else           return (uint32_t)r * 64  + ((g ^ (uint32_t)((r >> 1) & 3)) << 4);
    };

    auto load_chunk = [&](int s, int c) {
        const int kof = c * KCH;
        const uint32_t sb = smb + (uint32_t)s * STG_BYTES;
        for (int idx = tid; idx < 2 * 128 * GPC; idx += 256) {
            int half = idx / (128 * GPC);
            int j = idx - half * (128 * GPC);
            int r = j / GPC, g = j - r * GPC;
            cpa(sb + (uint32_t)half * ABYTES + swof(r, (uint32_t)g),
                (half ? AL : AH) + (size_t)(mrow0 + r) * lda + kof + g * 8);
        }
        for (int idx = tid; idx < 2 * NTILE * GPC; idx += 256) {
            int half = idx / (NTILE * GPC);
            int j = idx - half * (NTILE * GPC);
            int r = j / GPC, g = j - r * GPC;
            cpa(sb + 2 * ABYTES + (uint32_t)half * BBYTES + swof(r, (uint32_t)g),
                (half ? BL : BH) + (size_t)(nrow0 + r) * ldb + kof + g * 8);
        }
    };

    const int mw = wid & 1, nw = wid >> 1;
    const int mbase = mw * 64, nbase = nw * (NT * 8);
    const int rA0 = mbase + (l & 7) + ((l >> 3) & 1) * 8;
    const int rB0 = nbase + (l & 7) + ((l >> 3) & 1) * 8;
    const int gsel = l >> 4;

    float acc[4][NT][4];
#pragma unroll
    for (int a = 0; a < 4; a++)
#pragma unroll
        for (int b = 0; b < NT; b++)
#pragma unroll
            for (int c = 0; c < 4; c++) acc[a][b][c] = 0.0f;

    auto compute_kk = [&](int s, int kk) {
        const uint32_t base = smb + (uint32_t)s * STG_BYTES;
        const uint32_t g = 2 * kk + gsel;
        uint32_t ah[4][4], al_[4][4];
#pragma unroll
        for (int mt = 0; mt < 4; mt++) {
            uint32_t addr = base + swof(rA0 + mt * 16, g);
            ldsm4(ah[mt], addr);
            ldsm4(al_[mt], addr + ABYTES);
        }
#pragma unroll
        for (int p = 0; p < NT / 2; p++) {
            uint32_t t0[4], t1[4];
            uint32_t addr = base + 2 * ABYTES + swof(rB0 + p * 16, g);
            ldsm4(t0, addr);
            ldsm4(t1, addr + BBYTES);
            uint32_t bh0[2] = {t0[0], t0[2]}, bh1[2] = {t0[1], t0[3]};
            uint32_t bl0[2] = {t1[0], t1[2]}, bl1[2] = {t1[1], t1[3]};
#pragma unroll
            for (int mt = 0; mt < 4; mt++) {
                mma16816(acc[mt][2 * p],     ah[mt],  bh0);
                mma16816(acc[mt][2 * p],     ah[mt],  bl0);
                mma16816(acc[mt][2 * p],     al_[mt], bh0);
                mma16816(acc[mt][2 * p + 1], ah[mt],  bh1);
                mma16816(acc[mt][2 * p + 1], ah[mt],  bl1);
                mma16816(acc[mt][2 * p + 1], al_[mt], bh1);
            }
        }
    };

    // ---- pipeline: prologue commits exactly STAGES-1 groups (some empty) ----
#pragma unroll
    for (int s = 0; s < STAGES - 1; s++) {
        if (s < KB) load_chunk(s, s);
        CP_COMMIT();
    }
    for (int c = 0; c < KB; c++) {
        const int s = c % STAGES;
        if (STAGES == 4) { CP_WAIT2(); } else if (STAGES == 3) { CP_WAIT1(); } else { CP_WAIT0(); }
        __syncthreads();
        if (c + STAGES - 1 < KB) load_chunk((c + STAGES - 1) % STAGES, c + STAGES - 1);
        CP_COMMIT();
#pragma unroll
        for (int kk = 0; kk < KCH / 16; kk++) compute_kk(s, kk);
        __syncthreads();
    }

    const int rr = l >> 2, cc = (l & 3) * 2;

    if (WEFF) {
        // acc[mt][nt] = (lora_A @ lora_B)[kk=col][n=row].  Load W tile transposed.
        __syncthreads();
        float* Wt = (float*)smc;   // [n_local][kk_local], stride 129
        for (int i = tid; i < 128 * 128; i += 256) {
            int kk = i >> 7, n = i & 127;
            Wt[n * 129 + kk] = Wsrc[(size_t)(nrow0 + kk) * TOT + mrow0 + n];
        }
        __syncthreads();
#pragma unroll
        for (int mt = 0; mt < 4; mt++)
#pragma unroll
            for (int h = 0; h < 2; h++) {
                const int rl = mbase + mt * 16 + rr + h * 8;
                const size_t r = (size_t)(mrow0 + rl);
#pragma unroll
                for (int nt = 0; nt < NT; nt++) {
                    const int cl = nbase + nt * 8 + cc;
                    const int cx = nrow0 + cl;
                    float w0 = Wt[rl * 129 + cl];
                    float w1 = Wt[rl * 129 + cl + 1];
                    float v0 = (w0 == 0.0f) ? 0.0f : (w0 + 2.0f * acc[mt][nt][h * 2 + 0]);
                    float v1 = (w1 == 0.0f) ? 0.0f : (w1 + 2.0f * acc[mt][nt][h * 2 + 1]);
                    uint32_t ph, pl;
                    pack2(v0, v1, ph, pl);
                    *(uint32_t*)((char*)PH + (r * ldP + cx) * 2) = ph;
                    *(uint32_t*)((char*)PL + (r * ldP + cx) * 2) = pl;
                }
            }
        return;
    }

    const int growb = mrow0 + mbase;
    const int gcolb = nrow0 + nbase;
#pragma unroll
    for (int mt = 0; mt < 4; mt++)
#pragma unroll
        for (int h = 0; h < 2; h++) {
            const int r = growb + mt * 16 + rr + h * 8;
#pragma unroll
            for (int nt = 0; nt < NT; nt++) {
                const int cx = gcolb + nt * 8 + cc;
                float v0 = acc[mt][nt][h * 2 + 0];
                float v1 = acc[mt][nt][h * 2 + 1];
                if (bias && cx < ncolF) {
                    float2 bv = *(const float2*)(bias + cx);
                    v0 += bv.x; v1 += bv.y;
                }
                if (addH && cx < add_cols) {
                    uint32_t uh = *(const uint32_t*)((const char*)addH + ((size_t)r * ld_add + cx) * 2);
                    uint32_t ul = *(const uint32_t*)((const char*)addL + ((size_t)r * ld_add + cx) * 2);
                    v0 += bflo(uh) + bflo(ul);
                    v1 += bfhi(uh) + bfhi(ul);
                }
                if (do_relu) { v0 = fmaxf(v0, 0.0f); v1 = fmaxf(v1, 0.0f); }
                if (outF && cx < ncolF)
                    *(float2*)(outF + (size_t)r * ldF + cx) = make_float2(v0, v1);
                if (PH) {
                    uint32_t ph, pl;
                    pack2(v0, v1, ph, pl);
                    *(uint32_t*)((char*)PH + ((size_t)r * ldP + cx) * 2) = ph;
                    *(uint32_t*)((char*)PL + ((size_t)r * ldP + cx) * 2) = pl;
                }
            }
        }
}

// ---------------- launch ----------------------------------------------------
extern "C" void kernel_launch(void* const* d_in, const int* in_sizes, int n_in,
                              void* d_out, int out_size)
{
    const float* x      = (const float*)d_in[0];
    ConvPtrs cw;
    for (int i = 0; i < 8; i++) cw.w[i] = (const float*)d_in[1 + i];
    const float* conv_b = (const float*)d_in[9];
    const float* W      = (const float*)d_in[10];
    const float* lora_A = (const float*)d_in[11];
    const float* lora_B = (const float*)d_in[12];
    const float* ip_w   = (const float*)d_in[13];
    const float* ip_b   = (const float*)d_in[14];
    const float* out_w  = (const float*)d_in[15];
    const float* out_b  = (const float*)d_in[16];
    float* out = (float*)d_out;

    __nv_bfloat16 *featH, *featL, *ipwH, *ipwL, *WH, *WL, *owH, *owL;
    __nv_bfloat16 *P0H, *P0L, *P1H, *P1L, *OPH, *OPL, *laH, *laL, *lbtH, *lbtL;
    cudaGetSymbolAddress((void**)&featH, g_featH);
    cudaGetSymbolAddress((void**)&featL, g_featL);
    cudaGetSymbolAddress((void**)&ipwH,  g_ipwH);
    cudaGetSymbolAddress((void**)&ipwL,  g_ipwL);
    cudaGetSymbolAddress((void**)&WH,    g_WH);
    cudaGetSymbolAddress((void**)&WL,    g_WL);
    cudaGetSymbolAddress((void**)&owH,   g_owH);
    cudaGetSymbolAddress((void**)&owL,   g_owL);
    cudaGetSymbolAddress((void**)&P0H,   g_P0H);
    cudaGetSymbolAddress((void**)&P0L,   g_P0L);
    cudaGetSymbolAddress((void**)&P1H,   g_P1H);
    cudaGetSymbolAddress((void**)&P1L,   g_P1L);
    cudaGetSymbolAddress((void**)&OPH,   g_OPH);
    cudaGetSymbolAddress((void**)&OPL,   g_OPL);
    cudaGetSymbolAddress((void**)&laH,   g_laH);
    cudaGetSymbolAddress((void**)&laL,   g_laL);
    cudaGetSymbolAddress((void**)&lbtH,  g_lbtH);
    cudaGetSymbolAddress((void**)&lbtL,  g_lbtL);

    const int SMEM4 = 3 * (2 * 128 * 64 * 2 + 2 * 128 * 64 * 2);   // 3*64KB = 196608
    const int SMEM8 = 4 * (2 * 128 * 32 * 2 + 2 * 256 * 32 * 2);   // 4*48KB = 196608
    cudaFuncSetAttribute(mma_gemm<4, 3, 64, false>, cudaFuncAttributeMaxDynamicSharedMemorySize, SMEM4);
    cudaFuncSetAttribute(mma_gemm<8, 4, 32, false>, cudaFuncAttributeMaxDynamicSharedMemorySize, SMEM8);
    cudaFuncSetAttribute(mma_gemm<4, 3, 64, true>,  cudaFuncAttributeMaxDynamicSharedMemorySize, SMEM4);

    // ---- prologue packs (ordered so launch idx 3 = t0 GEMM for ncu) ----
    conv_feat_kernel<<<BATCH, 256>>>(x, cw, conv_b, featH, featL);                       // 0
    pack_wT<<<dim3(CNNOUT / 64, SEN / 64), 256>>>(ip_w, SEN, SEN, CNNOUT, ipwH, ipwL);   // 1
    pack_wT<<<dim3(1024 / 64, NOUT_PAD / 64), 256>>>(out_w, NOUT, NOUT, 1024, owH, owL); // 2

    // ---- t0: state0 = relu(feat @ ip_w + b) -> P0 (cols < 1024) ---- (launch 3)
    mma_gemm<4, 3, 64, false><<<dim3(SEN / 128, 8), 256, SMEM4>>>(
        featH, featL, CNNOUT, ipwH, ipwL, CNNOUT, CNNOUT,
        ip_b, nullptr, nullptr, 0, 0, 1,
        nullptr, 0, SEN, P0H, P0L, TOT, nullptr);

    // ---- lora packs + W_eff^T ----
    split_copy<<<(TOT * 64 / 8 + 255) / 256, 256>>>(lora_A, laH, laL, TOT * 64 / 8);     // 4
    pack_wT<<<dim3(1, TOT / 64), 256>>>(lora_B, TOT, TOT, 64, lbtH, lbtL);               // 5
    mma_gemm<4, 3, 64, true><<<dim3(32, 32), 256, SMEM4>>>(                              // 6
        lbtH, lbtL, 64, laH, laL, 64, 64,
        nullptr, nullptr, nullptr, 0, 0, 0,
        nullptr, 0, 0, WH, WL, TOT, W);

    // ---- t1 (K = 1024) ----
    mma_gemm<8, 4, 32, false><<<dim3(TOT / 256, 8), 256, SMEM8>>>(
        P0H, P0L, TOT, WH, WL, TOT, 1024,
        nullptr, P0H, P0L, 1024, TOT, 1,
        nullptr, 0, 0, P1H, P1L, TOT, nullptr);

    // ---- t2 ----
    mma_gemm<8, 4, 32, false><<<dim3(TOT / 256, 8), 256, SMEM8>>>(
        P1H, P1L, TOT, WH, WL, TOT, TOT,
        nullptr, P1H, P1L, TOT, TOT, 1,
        nullptr, 0, 0, P0H, P0L, TOT, nullptr);

    // ---- t3 ----
    mma_gemm<8, 4, 32, false><<<dim3(TOT / 256, 8), 256, SMEM8>>>(
        P0H, P0L, TOT, WH, WL, TOT, TOT,
        nullptr, P0H, P0L, TOT, TOT, 1,
        nullptr, 0, 0, P1H, P1L, TOT, nullptr);

    // ---- t4 (N = 1024: only cols [3072,4096) feed the head) ----
    mma_gemm<4, 3, 64, false><<<dim3(1024 / 128, 8), 256, SMEM4>>>(
        P1H, P1L, TOT, WH + (size_t)3072 * TOT, WL + (size_t)3072 * TOT, TOT, TOT,
        nullptr, P1H + 3072, P1L + 3072, 1024, TOT, 1,
        nullptr, 0, 0, OPH, OPL, 1024, nullptr);

    // ---- out = O @ out_w + out_b ----
    mma_gemm<4, 3, 64, false><<<dim3(NOUT_PAD / 128, 8), 256, SMEM4>>>(
        OPH, OPL, 1024, owH, owL, 1024, 1024,
        out_b, nullptr, nullptr, 0, 0, 0,
        out, NOUT, NOUT, nullptr, nullptr, 0, nullptr);
}

// round 7
// speedup vs baseline: 1.1169x; 1.1169x over previous
#include <cuda_runtime.h>
#include <cuda_bf16.h>
#include <cstdint>

#define BATCH    1024
#define TOT      4096
#define SEN      1024
#define CNNOUT   3264
#define NOUT     1968
#define NOUT_PAD 2048

// ---------------- scratch device globals (no allocations) -------------------
__device__ __align__(256) __nv_bfloat16 g_featH[(size_t)BATCH * CNNOUT];
__device__ __align__(256) __nv_bfloat16 g_featL[(size_t)BATCH * CNNOUT];
__device__ __align__(256) __nv_bfloat16 g_ipwH [(size_t)SEN * CNNOUT];
__device__ __align__(256) __nv_bfloat16 g_ipwL [(size_t)SEN * CNNOUT];
__device__ __align__(256) __nv_bfloat16 g_WH   [(size_t)TOT * TOT];
__device__ __align__(256) __nv_bfloat16 g_WL   [(size_t)TOT * TOT];
__device__ __align__(256) __nv_bfloat16 g_owH  [(size_t)NOUT_PAD * 1024];
__device__ __align__(256) __nv_bfloat16 g_owL  [(size_t)NOUT_PAD * 1024];
__device__ __align__(256) __nv_bfloat16 g_P0H  [(size_t)BATCH * TOT];
__device__ __align__(256) __nv_bfloat16 g_P0L  [(size_t)BATCH * TOT];
__device__ __align__(256) __nv_bfloat16 g_P1H  [(size_t)BATCH * TOT];
__device__ __align__(256) __nv_bfloat16 g_P1L  [(size_t)BATCH * TOT];
__device__ __align__(256) __nv_bfloat16 g_OPH  [(size_t)BATCH * 1024];
__device__ __align__(256) __nv_bfloat16 g_OPL  [(size_t)BATCH * 1024];
__device__ __align__(256) __nv_bfloat16 g_laH [(size_t)TOT * 64];
__device__ __align__(256) __nv_bfloat16 g_laL [(size_t)TOT * 64];
__device__ __align__(256) __nv_bfloat16 g_lbtH[(size_t)TOT * 64];
__device__ __align__(256) __nv_bfloat16 g_lbtL[(size_t)TOT * 64];
__device__ __align__(256) float g_part[(size_t)3 * BATCH * 1024];   // split-K partials

// ---------------- helpers ----------------------------------------------------
__device__ __forceinline__ uint32_t smem_u32(const void* p) {
    uint32_t a;
    asm("{ .reg .u64 t; cvta.to.shared.u64 t, %1; cvt.u32.u64 %0, t; }" : "=r"(a) : "l"(p));
    return a;
}
__device__ __forceinline__ void cpa(uint32_t dst, const void* src) {
    asm volatile("cp.async.cg.shared.global [%0], [%1], 16;" :: "r"(dst), "l"(src));
}
#define CP_COMMIT() asm volatile("cp.async.commit_group;")
#define CP_WAIT0()  asm volatile("cp.async.wait_group 0;")
#define CP_WAIT1()  asm volatile("cp.async.wait_group 1;")

__device__ __forceinline__ void ldsm4(uint32_t* r, uint32_t addr) {
    asm volatile("ldmatrix.sync.aligned.m8n8.x4.shared.b16 {%0,%1,%2,%3}, [%4];"
                 : "=r"(r[0]), "=r"(r[1]), "=r"(r[2]), "=r"(r[3]) : "r"(addr));
}
__device__ __forceinline__ void mma16816(float* c, const uint32_t* a, const uint32_t* b) {
    asm volatile("mma.sync.aligned.m16n8k16.row.col.f32.bf16.bf16.f32 "
                 "{%0,%1,%2,%3}, {%4,%5,%6,%7}, {%8,%9}, {%0,%1,%2,%3};"
                 : "+f"(c[0]), "+f"(c[1]), "+f"(c[2]), "+f"(c[3])
                 : "r"(a[0]), "r"(a[1]), "r"(a[2]), "r"(a[3]), "r"(b[0]), "r"(b[1]));
}

__device__ __forceinline__ void split8(const float* v, uint4& uh, uint4& ul) {
    uint32_t h[4], l[4];
#pragma unroll
    for (int q = 0; q < 4; q++) {
        __nv_bfloat16 b0 = __float2bfloat16(v[2 * q]);
        __nv_bfloat16 b1 = __float2bfloat16(v[2 * q + 1]);
        float r0 = v[2 * q]     - __bfloat162float(b0);
        float r1 = v[2 * q + 1] - __bfloat162float(b1);
        __nv_bfloat16 c0 = __float2bfloat16(r0);
        __nv_bfloat16 c1 = __float2bfloat16(r1);
        h[q] = (uint32_t)__bfloat16_as_ushort(b0) | ((uint32_t)__bfloat16_as_ushort(b1) << 16);
        l[q] = (uint32_t)__bfloat16_as_ushort(c0) | ((uint32_t)__bfloat16_as_ushort(c1) << 16);
    }
    uh = make_uint4(h[0], h[1], h[2], h[3]);
    ul = make_uint4(l[0], l[1], l[2], l[3]);
}
__device__ __forceinline__ void pack2(float v0, float v1, uint32_t& ph, uint32_t& pl) {
    __nv_bfloat16 h0 = __float2bfloat16(v0);
    __nv_bfloat16 h1 = __float2bfloat16(v1);
    __nv_bfloat16 q0 = __float2bfloat16(v0 - __bfloat162float(h0));
    __nv_bfloat16 q1 = __float2bfloat16(v1 - __bfloat162float(h1));
    ph = (uint32_t)__bfloat16_as_ushort(h0) | ((uint32_t)__bfloat16_as_ushort(h1) << 16);
    pl = (uint32_t)__bfloat16_as_ushort(q0) | ((uint32_t)__bfloat16_as_ushort(q1) << 16);
}
__device__ __forceinline__ float bflo(uint32_t u) {
    return __bfloat162float(__ushort_as_bfloat16((unsigned short)(u & 0xFFFF)));
}
__device__ __forceinline__ float bfhi(uint32_t u) {
    return __bfloat162float(__ushort_as_bfloat16((unsigned short)(u >> 16)));
}

// ---------------- conv feature extraction -> hi/lo row-major ----------------
struct ConvPtrs { const float* w[8]; };

__global__ void conv_feat_kernel(const float* __restrict__ x, ConvPtrs cw,
                                 const float* __restrict__ conv_b,
                                 __nv_bfloat16* __restrict__ fH,
                                 __nv_bfloat16* __restrict__ fL)
{
    __shared__ float xs[512];
    const int b = blockIdx.x;
    const float* xb = x + b * 512;
    for (int i = threadIdx.x; i < 512; i += 256) xs[i] = xb[i];
    __syncthreads();

    const int offs[9] = {0, 1024, 1808, 2384, 2784, 3040, 3184, 3248, 3264};

    for (int o = threadIdx.x; o < CNNOUT; o += 256) {
        int k = 1;
        while (o >= offs[k]) k++;
        int local = o - offs[k - 1];
        int H = 9 - k;
        int f = local / (H * H);
        int rem = local - f * H * H;
        int i0 = rem / H;
        int j0 = rem - i0 * H;

        const float* w = cw.w[k - 1] + f * 8 * k * k;
        float acc = conv_b[(k - 1) * 16 + f];
        for (int c = 0; c < 8; c++) {
            const float* wc = w + c * k * k;
            for (int p = 0; p < k; p++)
                for (int q = 0; q < k; q++)
                    acc += xs[((i0 + p) * 8 + (j0 + q)) * 8 + c] * wc[p * k + q];
        }
        float e = fmaxf(acc, 0.0f);
        __nv_bfloat16 bh = __float2bfloat16(e);
        __nv_bfloat16 bl = __float2bfloat16(e - __bfloat162float(bh));
        fH[(size_t)b * CNNOUT + o] = bh;
        fL[(size_t)b * CNNOUT + o] = bl;
    }
}

// ---------------- pack [K,N] fp32 weight transposed -> [N,K] hi/lo bf16 -----
__global__ __launch_bounds__(256) void pack_wT(const float* __restrict__ w,
                                               int ldw, int ntrue, int ldk,
                                               __nv_bfloat16* __restrict__ H,
                                               __nv_bfloat16* __restrict__ L)
{
    __shared__ float sm[64 * 65];
    const int k0 = blockIdx.x * 64, n0 = blockIdx.y * 64;
    const int tid = threadIdx.x;

    for (int i = tid; i < 4096; i += 256) {
        int k = i >> 6, n = i & 63;
        int gn = n0 + n;
        sm[k * 65 + n] = (gn < ntrue) ? w[(size_t)(k0 + k) * ldw + gn] : 0.0f;
    }
    __syncthreads();

    for (int it = tid; it < 512; it += 256) {
        int n = it & 63, kg = it >> 6;
        float v[8];
#pragma unroll
        for (int j = 0; j < 8; j++) v[j] = sm[(kg * 8 + j) * 65 + n];
        uint4 uh, ul;
        split8(v, uh, ul);
        size_t o = (size_t)(n0 + n) * ldk + k0 + kg * 8;
        *(uint4*)((char*)H + o * 2) = uh;
        *(uint4*)((char*)L + o * 2) = ul;
    }
}

// ---------------- straight split-copy fp32 -> hi/lo bf16 --------------------
__global__ void split_copy(const float* __restrict__ in,
                           __nv_bfloat16* __restrict__ H,
                           __nv_bfloat16* __restrict__ L, int n8)
{
    int i = blockIdx.x * blockDim.x + threadIdx.x;
    if (i >= n8) return;
    float v[8];
    *(float4*)(v)     = *(const float4*)(in + (size_t)i * 8);
    *(float4*)(v + 4) = *(const float4*)(in + (size_t)i * 8 + 4);
    uint4 uh, ul;
    split8(v, uh, ul);
    *(uint4*)((char*)H + (size_t)i * 16) = uh;
    *(uint4*)((char*)L + (size_t)i * 16) = ul;
}

// ---------------- split-K reduce + bias/addend/relu/pack epilogue -----------
__global__ __launch_bounds__(256) void epi_reduce(
    const float* __restrict__ part, int nz,
    const float* __restrict__ bias,
    const __nv_bfloat16* __restrict__ addH, const __nv_bfloat16* __restrict__ addL,
    int ld_add,
    __nv_bfloat16* __restrict__ PH, __nv_bfloat16* __restrict__ PL, int ldP)
{
    const int i = blockIdx.x * blockDim.x + threadIdx.x;   // over 1024*512
    const int r = i >> 9;
    const int c2 = (i & 511) << 1;
    float v0 = 0.0f, v1 = 0.0f;
    for (int z = 0; z < nz; z++) {
        float2 p = *(const float2*)(part + (size_t)z * BATCH * 1024 + (size_t)r * 1024 + c2);
        v0 += p.x; v1 += p.y;
    }
    if (bias) {
        float2 b = *(const float2*)(bias + c2);
        v0 += b.x; v1 += b.y;
    }
    if (addH) {
        uint32_t uh = *(const uint32_t*)((const char*)addH + ((size_t)r * ld_add + c2) * 2);
        uint32_t ul = *(const uint32_t*)((const char*)addL + ((size_t)r * ld_add + c2) * 2);
        v0 += bflo(uh) + bflo(ul);
        v1 += bfhi(uh) + bfhi(ul);
    }
    v0 = fmaxf(v0, 0.0f); v1 = fmaxf(v1, 0.0f);
    uint32_t ph, pl;
    pack2(v0, v1, ph, pl);
    *(uint32_t*)((char*)PH + ((size_t)r * ldP + c2) * 2) = ph;
    *(uint32_t*)((char*)PL + ((size_t)r * ldP + c2) * 2) = pl;
}

// ---------------- mma.sync bf16-split GEMM ----------------------------------
// WN = warps in N (4 or 8). CTA = 2(M) x WN warps, threads = 64*WN.
// Tile: 128 x (32*WN). Warp tile 64x32. KCH=64, STAGES ring buffers.
// 3-term split (drop lo*lo). blockIdx.z = split-K slice (A/B k-offset z*K,
// partial written to outF + z*partStride).
// WEFF: acc = lora product; epilogue mask(W)*(W + 2*acc) -> packed Wt.
template<int WN, int STAGES, bool WEFF>
__global__ __launch_bounds__(64 * WN, 1)
void mma_gemm(const __nv_bfloat16* __restrict__ AH, const __nv_bfloat16* __restrict__ AL, int lda,
              const __nv_bfloat16* __restrict__ BH, const __nv_bfloat16* __restrict__ BL, int ldb,
              int K,
              const float* __restrict__ bias,
              const __nv_bfloat16* __restrict__ addH, const __nv_bfloat16* __restrict__ addL,
              int add_cols, int ld_add, int do_relu,
              float* __restrict__ outF, int ldF, int ncolF,
              __nv_bfloat16* __restrict__ PH, __nv_bfloat16* __restrict__ PL, int ldP,
              const float* __restrict__ Wsrc, int partStride)
{
    constexpr int THREADS = 64 * WN;
    constexpr int NTILE   = 32 * WN;
    constexpr int AHALF   = 128 * 64 * 2;      // 16 KB
    constexpr int BHALF   = NTILE * 64 * 2;
    constexpr int STG     = 2 * AHALF + 2 * BHALF;
    extern __shared__ __align__(128) char smc[];

    const int tid = threadIdx.x, l = tid & 31, wid = tid >> 5;
    const int nblk = blockIdx.x, mblk = blockIdx.y, zo = blockIdx.z;
    const int KB = K >> 6;
    const uint32_t smb = smem_u32(smc);
    const int mrow0 = mblk * 128;
    const int nrow0 = nblk * NTILE;

    AH += (size_t)zo * K; AL += (size_t)zo * K;
    BH += (size_t)zo * K; BL += (size_t)zo * K;
    if (outF) outF += (size_t)zo * partStride;

    auto swof = [](int r, uint32_t g) -> uint32_t {
        return (uint32_t)r * 128 + ((g ^ (uint32_t)(r & 7)) << 4);
    };

    auto load_chunk = [&](int s, int c) {
        const int kof = c * 64;
        const uint32_t sb = smb + (uint32_t)s * STG;
        for (int idx = tid; idx < 2 * 128 * 8; idx += THREADS) {
            int half = idx >> 10;
            int j = idx & 1023;
            int r = j >> 3, g = j & 7;
            cpa(sb + (uint32_t)half * AHALF + swof(r, (uint32_t)g),
                (half ? AL : AH) + (size_t)(mrow0 + r) * lda + kof + g * 8);
        }
        for (int idx = tid; idx < 2 * NTILE * 8; idx += THREADS) {
            int half = idx / (NTILE * 8);
            int j = idx - half * (NTILE * 8);
            int r = j >> 3, g = j & 7;
            cpa(sb + 2 * AHALF + (uint32_t)half * BHALF + swof(r, (uint32_t)g),
                (half ? BL : BH) + (size_t)(nrow0 + r) * ldb + kof + g * 8);
        }
    };

    const int mw = wid & 1, nw = wid >> 1;
    const int mbase = mw * 64, nbase = nw * 32;
    const int rA0 = mbase + (l & 7) + ((l >> 3) & 1) * 8;
    const int rB0 = nbase + (l & 7) + ((l >> 3) & 1) * 8;
    const int gsel = l >> 4;

    float acc[4][4][4];
#pragma unroll
    for (int a = 0; a < 4; a++)
#pragma unroll
        for (int b = 0; b < 4; b++)
#pragma unroll
            for (int c = 0; c < 4; c++) acc[a][b][c] = 0.0f;

    auto compute_kk = [&](int s, int kk) {
        const uint32_t base = smb + (uint32_t)s * STG;
        const uint32_t g = 2 * kk + gsel;
        uint32_t bh[4][2], bl[4][2];
#pragma unroll
        for (int p = 0; p < 2; p++) {
            uint32_t t0[4], t1[4];
            uint32_t addr = base + 2 * AHALF + swof(rB0 + p * 16, g);
            ldsm4(t0, addr);
            ldsm4(t1, addr + BHALF);
            bh[2 * p][0] = t0[0]; bh[2 * p][1] = t0[2];
            bh[2 * p + 1][0] = t0[1]; bh[2 * p + 1][1] = t0[3];
            bl[2 * p][0] = t1[0]; bl[2 * p][1] = t1[2];
            bl[2 * p + 1][0] = t1[1]; bl[2 * p + 1][1] = t1[3];
        }
#pragma unroll
        for (int mt = 0; mt < 4; mt++) {
            uint32_t ah[4], al_[4];
            uint32_t addr = base + swof(rA0 + mt * 16, g);
            ldsm4(ah, addr);
            ldsm4(al_, addr + AHALF);
#pragma unroll
            for (int nt = 0; nt < 4; nt++) mma16816(acc[mt][nt], ah, bh[nt]);
#pragma unroll
            for (int nt = 0; nt < 4; nt++) mma16816(acc[mt][nt], ah, bl[nt]);
#pragma unroll
            for (int nt = 0; nt < 4; nt++) mma16816(acc[mt][nt], al_, bh[nt]);
        }
    };

    // pipeline: prologue commits exactly STAGES-1 groups (empty ones are
    // in-order fences; required when KB < STAGES-1)
#pragma unroll
    for (int s = 0; s < STAGES - 1; s++) {
        if (s < KB) load_chunk(s, s);
        CP_COMMIT();
    }
    for (int c = 0; c < KB; c++) {
        const int s = c % STAGES;
        if (STAGES == 3) { CP_WAIT1(); } else { CP_WAIT0(); }
        __syncthreads();
        if (c + STAGES - 1 < KB) load_chunk((c + STAGES - 1) % STAGES, c + STAGES - 1);
        CP_COMMIT();
#pragma unroll
        for (int kk = 0; kk < 4; kk++) compute_kk(s, kk);
        __syncthreads();
    }

    const int rr = l >> 2, cc = (l & 3) * 2;

    if (WEFF) {
        __syncthreads();
        float* Wt = (float*)smc;   // [n_local][kk_local], stride 129
        for (int i = tid; i < 128 * 128; i += THREADS) {
            int kk = i >> 7, n = i & 127;
            Wt[n * 129 + kk] = Wsrc[(size_t)(nrow0 + kk) * TOT + mrow0 + n];
        }
        __syncthreads();
#pragma unroll
        for (int mt = 0; mt < 4; mt++)
#pragma unroll
            for (int h = 0; h < 2; h++) {
                const int rl = mbase + mt * 16 + rr + h * 8;
                const size_t r = (size_t)(mrow0 + rl);
#pragma unroll
                for (int nt = 0; nt < 4; nt++) {
                    const int cl = nbase + nt * 8 + cc;
                    const int cx = nrow0 + cl;
                    float w0 = Wt[rl * 129 + cl];
                    float w1 = Wt[rl * 129 + cl + 1];
                    float v0 = (w0 == 0.0f) ? 0.0f : (w0 + 2.0f * acc[mt][nt][h * 2 + 0]);
                    float v1 = (w1 == 0.0f) ? 0.0f : (w1 + 2.0f * acc[mt][nt][h * 2 + 1]);
                    uint32_t ph, pl;
                    pack2(v0, v1, ph, pl);
                    *(uint32_t*)((char*)PH + (r * ldP + cx) * 2) = ph;
                    *(uint32_t*)((char*)PL + (r * ldP + cx) * 2) = pl;
                }
            }
        return;
    }

    const int growb = mrow0 + mbase;
    const int gcolb = nrow0 + nbase;
#pragma unroll
    for (int mt = 0; mt < 4; mt++)
#pragma unroll
        for (int h = 0; h < 2; h++) {
            const int r = growb + mt * 16 + rr + h * 8;
#pragma unroll
            for (int nt = 0; nt < 4; nt++) {
                const int cx = gcolb + nt * 8 + cc;
                float v0 = acc[mt][nt][h * 2 + 0];
                float v1 = acc[mt][nt][h * 2 + 1];
                if (bias && cx < ncolF) {
                    float2 bv = *(const float2*)(bias + cx);
                    v0 += bv.x; v1 += bv.y;
                }
                if (addH && cx < add_cols) {
                    uint32_t uh = *(const uint32_t*)((const char*)addH + ((size_t)r * ld_add + cx) * 2);
                    uint32_t ul = *(const uint32_t*)((const char*)addL + ((size_t)r * ld_add + cx) * 2);
                    v0 += bflo(uh) + bflo(ul);
                    v1 += bfhi(uh) + bfhi(ul);
                }
                if (do_relu) { v0 = fmaxf(v0, 0.0f); v1 = fmaxf(v1, 0.0f); }
                if (outF && cx < ncolF)
                    *(float2*)(outF + (size_t)r * ldF + cx) = make_float2(v0, v1);
                if (PH) {
                    uint32_t ph, pl;
                    pack2(v0, v1, ph, pl);
                    *(uint32_t*)((char*)PH + ((size_t)r * ldP + cx) * 2) = ph;
                    *(uint32_t*)((char*)PL + ((size_t)r * ldP + cx) * 2) = pl;
                }
            }
        }
}

// ---------------- launch ----------------------------------------------------
extern "C" void kernel_launch(void* const* d_in, const int* in_sizes, int n_in,
                              void* d_out, int out_size)
{
    const float* x      = (const float*)d_in[0];
    ConvPtrs cw;
    for (int i = 0; i < 8; i++) cw.w[i] = (const float*)d_in[1 + i];
    const float* conv_b = (const float*)d_in[9];
    const float* W      = (const float*)d_in[10];
    const float* lora_A = (const float*)d_in[11];
    const float* lora_B = (const float*)d_in[12];
    const float* ip_w   = (const float*)d_in[13];
    const float* ip_b   = (const float*)d_in[14];
    const float* out_w  = (const float*)d_in[15];
    const float* out_b  = (const float*)d_in[16];
    float* out = (float*)d_out;

    __nv_bfloat16 *featH, *featL, *ipwH, *ipwL, *WH, *WL, *owH, *owL;
    __nv_bfloat16 *P0H, *P0L, *P1H, *P1L, *OPH, *OPL, *laH, *laL, *lbtH, *lbtL;
    float* part;
    cudaGetSymbolAddress((void**)&featH, g_featH);
    cudaGetSymbolAddress((void**)&featL, g_featL);
    cudaGetSymbolAddress((void**)&ipwH,  g_ipwH);
    cudaGetSymbolAddress((void**)&ipwL,  g_ipwL);
    cudaGetSymbolAddress((void**)&WH,    g_WH);
    cudaGetSymbolAddress((void**)&WL,    g_WL);
    cudaGetSymbolAddress((void**)&owH,   g_owH);
    cudaGetSymbolAddress((void**)&owL,   g_owL);
    cudaGetSymbolAddress((void**)&P0H,   g_P0H);
    cudaGetSymbolAddress((void**)&P0L,   g_P0L);
    cudaGetSymbolAddress((void**)&P1H,   g_P1H);
    cudaGetSymbolAddress((void**)&P1L,   g_P1L);
    cudaGetSymbolAddress((void**)&OPH,   g_OPH);
    cudaGetSymbolAddress((void**)&OPL,   g_OPL);
    cudaGetSymbolAddress((void**)&laH,   g_laH);
    cudaGetSymbolAddress((void**)&laL,   g_laL);
    cudaGetSymbolAddress((void**)&lbtH,  g_lbtH);
    cudaGetSymbolAddress((void**)&lbtL,  g_lbtL);
    cudaGetSymbolAddress((void**)&part,  g_part);

    const int SMEM_S = 3 * (2 * 16384 + 2 * 16384);   // WN=4, 3 stages: 192 KB
    const int SMEM_B = 2 * (2 * 16384 + 2 * 32768);   // WN=8, 2 stages: 192 KB
    cudaFuncSetAttribute(mma_gemm<4, 3, false>, cudaFuncAttributeMaxDynamicSharedMemorySize, SMEM_S);
    cudaFuncSetAttribute(mma_gemm<4, 3, true>,  cudaFuncAttributeMaxDynamicSharedMemorySize, SMEM_S);
    cudaFuncSetAttribute(mma_gemm<8, 2, false>, cudaFuncAttributeMaxDynamicSharedMemorySize, SMEM_B);

    // 0: conv features
    conv_feat_kernel<<<BATCH, 256>>>(x, cw, conv_b, featH, featL);
    // 1: ip_w pack
    pack_wT<<<dim3(CNNOUT / 64, SEN / 64), 256>>>(ip_w, SEN, SEN, CNNOUT, ipwH, ipwL);
    // 2-3: lora packs
    split_copy<<<(TOT * 64 / 8 + 255) / 256, 256>>>(lora_A, laH, laL, TOT * 64 / 8);
    pack_wT<<<dim3(1, TOT / 64), 256>>>(lora_B, TOT, TOT, 64, lbtH, lbtL);
    // 4: W_eff^T (tensor-core lora product + fused mask/pack)
    mma_gemm<4, 3, true><<<dim3(32, 32), 256, SMEM_S>>>(
        lbtH, lbtL, 64, laH, laL, 64, 64,
        nullptr, nullptr, nullptr, 0, 0, 0,
        nullptr, 0, 0, WH, WL, TOT, W, 0);

    // 5: t0 GEMM split-K=3 (K = 3*1088) -> fp32 partials
    mma_gemm<4, 3, false><<<dim3(SEN / 128, 8, 3), 256, SMEM_S>>>(
        featH, featL, CNNOUT, ipwH, ipwL, CNNOUT, 1088,
        nullptr, nullptr, nullptr, 0, 0, 0,
        part, 1024, 1024, nullptr, nullptr, 0, nullptr, BATCH * 1024);
    // 6: reduce + bias + relu + pack -> P0 (cols < 1024)
    epi_reduce<<<2048, 256>>>(part, 3, ip_b, nullptr, nullptr, 0, P0H, P0L, TOT);

    // 7: t1 (K = 1024), 512-thread 128x256 tiles
    mma_gemm<8, 2, false><<<dim3(TOT / 256, 8), 512, SMEM_B>>>(
        P0H, P0L, TOT, WH, WL, TOT, 1024,
        nullptr, P0H, P0L, 1024, TOT, 1,
        nullptr, 0, 0, P1H, P1L, TOT, nullptr, 0);
    // 8: t2
    mma_gemm<8, 2, false><<<dim3(TOT / 256, 8), 512, SMEM_B>>>(
        P1H, P1L, TOT, WH, WL, TOT, TOT,
        nullptr, P1H, P1L, TOT, TOT, 1,
        nullptr, 0, 0, P0H, P0L, TOT, nullptr, 0);
    // 9: t3
    mma_gemm<8, 2, false><<<dim3(TOT / 256, 8), 512, SMEM_B>>>(
        P0H, P0L, TOT, WH, WL, TOT, TOT,
        nullptr, P0H, P0L, TOT, TOT, 1,
        nullptr, 0, 0, P1H, P1L, TOT, nullptr, 0);

    // 10: t4 GEMM split-K=2 (N = cols [3072,4096), K = 2*2048) -> partials
    mma_gemm<4, 3, false><<<dim3(8, 8, 2), 256, SMEM_S>>>(
        P1H, P1L, TOT, WH + (size_t)3072 * TOT, WL + (size_t)3072 * TOT, TOT, 2048,
        nullptr, nullptr, nullptr, 0, 0, 0,
        part, 1024, 1024, nullptr, nullptr, 0, nullptr, BATCH * 1024);
    // 11: reduce + addend(P1 slice) + relu + pack -> OP
    epi_reduce<<<2048, 256>>>(part, 2, nullptr, P1H + 3072, P1L + 3072, TOT, OPH, OPL, 1024);

    // 12: out_w pack
    pack_wT<<<dim3(1024 / 64, NOUT_PAD / 64), 256>>>(out_w, NOUT, NOUT, 1024, owH, owL);
    // 13: out = O @ out_w + out_b
    mma_gemm<4, 3, false><<<dim3(NOUT_PAD / 128, 8), 256, SMEM_S>>>(
        OPH, OPL, 1024, owH, owL, 1024, 1024,
        out_b, nullptr, nullptr, 0, 0, 0,
        out, NOUT, NOUT, nullptr, nullptr, 0, nullptr, 0);
}